// round 15
// baseline (speedup 1.0000x reference)
#include <cuda_runtime.h>
#include <math.h>
#include <stdint.h>

#define B_    32
#define NIN   1024
#define NHID  2048
#define NOUT  512
#define TT    256
#define KLEN  62          // truncated alpha kernel length (indices 0..61), tau=8
#define THETA 10.0f
#define PAD   64          // zero history rows in psp tile
#define CH    128         // k-chunk size for sparse GEMM
#define LROW  144         // list row bytes: u32 count @0, uint8 idx @4

// ---------------- scratch (alloc-free: __device__ globals) ----------------
__device__ float g_srm[64];
__device__ float g_ref[64];

__device__ float    g_w1t[(size_t)NIN * NHID];              // 8 MB  w1^T [i][h]
__device__ float    g_w2t[(size_t)NHID * NOUT];             // 4 MB  w2^T [h][o]
__device__ uint32_t g_mask1[(size_t)B_ * TT * (NIN / 32)];  // [b][t][kw]
__device__ uint32_t g_mask2[(size_t)B_ * TT * (NHID / 32)];
__device__ uint8_t  g_list1[(size_t)B_ * TT * (NIN / CH) * LROW];
__device__ uint8_t  g_list2[(size_t)B_ * TT * (NHID / CH) * LROW];
__device__ float    g_a1[(size_t)B_ * TT * NHID];           // 64 MB fc1 out
__device__ float    g_a2[(size_t)B_ * TT * NOUT];           // 16 MB fc2 out

// ---------------- helpers ---------------------------------------------------
__device__ __forceinline__ uint32_t smem_u32(const void* p) {
    uint32_t a;
    asm("{ .reg .u64 t; cvta.to.shared.u64 t, %1; cvt.u32.u64 %0, t; }"
        : "=r"(a) : "l"(p));
    return a;
}
__device__ __forceinline__ void cp16(uint32_t s, const void* g) {
    asm volatile("cp.async.cg.shared.global [%0], [%1], 16;" :: "r"(s), "l"(g));
}

// ---------------- kernel tables (match reference double-precision math) ----
__global__ void init_tables() {
    int k = threadIdx.x;
    if (k < 64) {
        double v = 0.0;
        if (k < KLEN) {
            double t = (double)k;
            v = (t / 8.0) * exp(1.0 - t / 8.0);
        }
        g_srm[k] = (float)v;
        g_ref[k] = (float)(-20.0 * v);
    }
}

// ---------------- weight transpose: out[c][r] = in[r][c] -------------------
__global__ __launch_bounds__(256) void transpose_w(const float* __restrict__ in,
                                                   float* __restrict__ out,
                                                   int R, int C) {
    __shared__ float tile[32][33];
    int c0 = blockIdx.x * 32;
    int r0 = blockIdx.y * 32;
    for (int r = threadIdx.y; r < 32; r += 8)
        tile[r][threadIdx.x] = in[(size_t)(r0 + r) * C + c0 + threadIdx.x];
    __syncthreads();
    for (int r = threadIdx.y; r < 32; r += 8)
        out[(size_t)(c0 + r) * R + r0 + threadIdx.x] = tile[threadIdx.x][r];
}

// ---------------- input spike masks: mask1[b][t][kw], bit l = x[b][kw*32+l][t]
__global__ __launch_bounds__(256) void build_mask1(const float* __restrict__ x,
                                                   uint32_t* __restrict__ mask) {
    __shared__ float tile[32][33];
    int b  = blockIdx.z;
    int i0 = blockIdx.y * 32;
    int t0 = blockIdx.x * 32;
    int tid = threadIdx.x;
    for (int idx = tid; idx < 1024; idx += 256) {
        int r = idx >> 5, c = idx & 31;
        tile[r][c] = x[((size_t)b * NIN + i0 + r) * TT + t0 + c];
    }
    __syncthreads();
    int w = tid >> 5, lane = tid & 31;
#pragma unroll
    for (int q = 0; q < 4; q++) {
        int t = w * 4 + q;
        uint32_t word = __ballot_sync(0xFFFFFFFFu, tile[lane][t] != 0.0f);
        if (lane == 0)
            mask[((size_t)b * TT + t0 + t) * (NIN / 32) + (i0 >> 5)] = word;
    }
}

// ---------------- masks -> chunk-local index lists -------------------------
template <int K>
__global__ __launch_bounds__(256) void list_build(const uint32_t* __restrict__ mask,
                                                  uint8_t* __restrict__ list) {
    int bt = blockIdx.x * 256 + threadIdx.x;          // 0 .. B_*TT-1
    constexpr int NCH = K / CH;
    const uint32_t* mr = mask + (size_t)bt * (K / 32);
    uint8_t* lr = list + (size_t)bt * NCH * LROW;
    for (int kc = 0; kc < NCH; kc++) {
        uint8_t* row = lr + kc * LROW + 4;
        int n = 0;
#pragma unroll
        for (int w = 0; w < CH / 32; w++) {
            uint32_t m = mr[kc * (CH / 32) + w];
            while (m) {
                int j = __ffs(m) - 1;
                m &= m - 1;
                row[n++] = (uint8_t)(w * 32 + j);
            }
        }
        while (n & 3) row[n++] = CH;                  // sentinel -> zero row
        *(uint32_t*)(lr + kc * LROW) = (uint32_t)n;
    }
}

// ---------------- exact sparse spike GEMM (list-driven, reg-staged) --------
// C[b][t][h] = sum over active k (ascending) of Wt[k][h]; bitwise identical to
// dense fp32 ascending-k accumulation (skipped terms exact zeros; sentinel
// adds exact +0.0 from the zero row).
// Block 256 thr, tile 64 t x 64 h.  Warp owns 8 t; lane owns 2 h (LDS.64).
// Weights: single smem buffer, but the NEXT chunk is prefetched into 32
// registers/thread (8 x LDG.128) a full compute-phase ahead, drained to smem
// at the chunk boundary -> L2 latency fully hidden, smem stays 51.5KB.
// Lists double-buffered via cp.async (prefetched during compute).
template <int K, int N>
__global__ __launch_bounds__(256) void sparse_add(const uint8_t* __restrict__ list,
                                                  const float* __restrict__ Wt,
                                                  float* __restrict__ C) {
    constexpr int HT   = 64;
    constexpr int NCH  = K / CH;
    constexpr int WSZ  = (CH + 1) * HT;  // floats: CH rows + zero row
    constexpr int LSZ  = 64 * LROW;      // bytes per list buffer
    extern __shared__ char smraw[];
    float*   wbuf = (float*)smraw;                     // single weight buffer
    uint8_t* lbuf = (uint8_t*)(smraw + WSZ * 4);       // [2][64][LROW]
    uint32_t sb   = smem_u32(smraw);
    const uint32_t LOFF = WSZ * 4;

    int b  = blockIdx.z;
    int t0 = blockIdx.y * 64;
    int h0 = blockIdx.x * HT;
    int tid = threadIdx.x, warp = tid >> 5, lane = tid & 31;

    // per-thread weight-staging coordinates (8 float4 slots per chunk)
    int wrow = tid >> 4;            // 0..15 (row stride 16 over iterations)
    int wc4  = (tid & 15) * 4;      // h offset within HT

    // zero row (row CH) — written once, never overwritten by loads
    for (int i = tid; i < HT; i += 256) wbuf[CH * HT + i] = 0.0f;

    auto load_l = [&](int kc, int buf) {
#pragma unroll
        for (int it = 0; it < 3; it++) {                      // 576 cp16 total
            int idx = tid + it * 256;
            if (idx < 64 * LROW / 16) {
                int t = idx / (LROW / 16), seg = idx % (LROW / 16);
                cp16(sb + LOFF + buf * LSZ + t * LROW + seg * 16,
                     list + ((size_t)((b * TT + t0 + t) * NCH + kc)) * LROW + seg * 16);
            }
        }
    };
    auto ldg_w = [&](float4* wr, int kc) {
#pragma unroll
        for (int it = 0; it < 8; it++)
            wr[it] = *(const float4*)(Wt + (size_t)(kc * CH + wrow + it * 16) * N
                                         + h0 + wc4);
    };
    auto sts_w = [&](const float4* wr) {
#pragma unroll
        for (int it = 0; it < 8; it++)
            *(float4*)(wbuf + (wrow + it * 16) * HT + wc4) = wr[it];
    };

    // prologue: chunk 0 weights (cp.async, exposed once) + chunk 0 lists
    load_l(0, 0);
#pragma unroll
    for (int it = 0; it < 8; it++) {
        int idx = tid + it * 256;
        int row = idx >> 4, c4 = idx & 15;
        cp16(sb + (uint32_t)(row * HT + c4 * 4) * 4,
             Wt + (size_t)row * N + h0 + c4 * 4);
    }
    asm volatile("cp.async.commit_group;" ::: "memory");
    asm volatile("cp.async.wait_group 0;" ::: "memory");
    __syncthreads();

    // register prefetch of chunk 1 weights (lands during chunk 0 compute)
    float4 wr[8];
    if (NCH > 1) ldg_w(wr, 1);

    float acc[8][2];
#pragma unroll
    for (int i = 0; i < 8; i++) { acc[i][0] = 0.0f; acc[i][1] = 0.0f; }

    for (int kc = 0; kc < NCH; kc++) {
        int buf = kc & 1;
        if (kc + 1 < NCH) {
            load_l(kc + 1, buf ^ 1);                  // prefetch next lists
            asm volatile("cp.async.commit_group;" ::: "memory");
        }

        const float* wb = wbuf + lane * 2;
#pragma unroll
        for (int tt = 0; tt < 8; tt++) {
            const uint8_t* lp = lbuf + buf * LSZ + (warp * 8 + tt) * LROW;
            int n = *(const uint32_t*)lp;             // padded, multiple of 4
            const uint8_t* ip = lp + 4;
            float a0 = acc[tt][0], a1 = acc[tt][1];
#pragma unroll 2
            for (int i = 0; i < n; i += 4) {
                uint32_t pk = *(const uint32_t*)(ip + i);
#pragma unroll
                for (int q = 0; q < 4; q++) {
                    int c = (pk >> (8 * q)) & 0xFF;   // 0..CH
                    float2 wv = *(const float2*)(wb + c * HT);
                    a0 += wv.x; a1 += wv.y;
                }
            }
            acc[tt][0] = a0; acc[tt][1] = a1;
        }

        if (kc + 1 < NCH) {
            __syncthreads();                          // WAR: wbuf fully consumed
            sts_w(wr);                                // regs -> wbuf (fast)
            if (kc + 2 < NCH) ldg_w(wr, kc + 2);      // prefetch next-next
            asm volatile("cp.async.wait_group 0;" ::: "memory");  // lists landed
            __syncthreads();                          // RAW: wbuf + lists ready
        }
    }

    float* Cb = C + ((size_t)b * TT + t0 + warp * 8) * N + h0 + lane * 2;
#pragma unroll
    for (int tt = 0; tt < 8; tt++)
        *(float2*)(Cb + (size_t)tt * N) = make_float2(acc[tt][0], acc[tt][1]);
}

// ---------------- fused PSP conv + threshold/refractory scan ---------------
template <bool MASKOUT>
__global__ __launch_bounds__(256) void psp_scan(const float* __restrict__ in,
                                                float* __restrict__ fout,
                                                uint32_t* __restrict__ mout,
                                                int C) {
    __shared__ float tile[TT + PAD][33];
    __shared__ float srm[64];
    __shared__ float ref[64];

    int b  = blockIdx.y;
    int c0 = blockIdx.x * 32;
    int tid = threadIdx.x;

    if (tid < 64)       srm[tid] = g_srm[tid];
    else if (tid < 128) ref[tid - 64] = g_ref[tid - 64];

    for (int idx = tid; idx < PAD * 32; idx += 256)
        tile[idx >> 5][idx & 31] = 0.0f;

    const float* pin = in + (size_t)b * TT * C + c0;
    for (int idx = tid; idx < TT * 32; idx += 256) {
        int t = idx >> 5, c = idx & 31;
        tile[PAD + t][c] = pin[(size_t)t * C + c];
    }
    __syncthreads();

    float acc[2][16];
    int cc[2], tt0[2];
#pragma unroll
    for (int j = 0; j < 2; j++) {
        int item = tid + 256 * j;
        int c  = item & 31;
        int t0 = (item >> 5) * 16;
        cc[j] = c; tt0[j] = t0;
#pragma unroll
        for (int i = 0; i < 16; i++) acc[j][i] = 0.0f;

#pragma unroll
        for (int g = 0; g < 4; g++) {
            float v[31];
            int base = PAD + t0 - 16 * (g + 1);
#pragma unroll
            for (int q = 0; q < 31; q++) v[q] = tile[base + q][c];
            int kkmax = (g == 3) ? 13 : 16;
#pragma unroll
            for (int kk = 1; kk <= 16; kk++) {
                if (kk > kkmax) break;
                float s = srm[16 * g + kk];
#pragma unroll
                for (int i = 0; i < 16; i++)
                    acc[j][i] += s * v[16 + i - kk];
            }
        }
    }
    __syncthreads();

#pragma unroll
    for (int j = 0; j < 2; j++)
#pragma unroll
        for (int i = 0; i < 16; i++)
            tile[PAD + tt0[j] + i][cc[j]] = acc[j][i];
    __syncthreads();

    // scan: one thread per channel, 61-bit spike-history mask.
    if (tid < 32) {
        int c = tid;
        unsigned long long hist = 0ull;
        const unsigned long long M61 = (1ull << 61) - 1ull;
        for (int t8 = 0; t8 < TT; t8 += 8) {
            float u8[8];
#pragma unroll
            for (int q = 0; q < 8; q++) u8[q] = tile[PAD + t8 + q][c];
#pragma unroll
            for (int q = 0; q < 8; q++) {
                float u = u8[q];
                unsigned long long m = hist;
                while (m) {
                    int j = __ffsll((long long)m) - 1;   // age = j+1
                    u += ref[j + 1];
                    m &= m - 1;
                }
                unsigned long long s = (u >= THETA) ? 1ull : 0ull;
                hist = ((hist << 1) | s) & M61;
                tile[PAD + t8 + q][c] = (float)s;
            }
        }
    }
    __syncthreads();

    if (MASKOUT) {
        int w = tid >> 5, lane = tid & 31;
#pragma unroll
        for (int q = 0; q < 32; q++) {
            int t = w * 32 + q;
            uint32_t word = __ballot_sync(0xFFFFFFFFu, tile[PAD + t][lane] != 0.0f);
            if (lane == 0)
                mout[((size_t)b * TT + t) * (C / 32) + (c0 >> 5)] = word;
        }
    } else {
        for (int idx = tid; idx < TT * 32; idx += 256) {
            int t = idx & 255, c = idx >> 8;        // t-fast: coalesced STG
            fout[((size_t)b * C + c0 + c) * TT + t] = tile[PAD + t][c];
        }
    }
}

// ---------------- launch ----------------------------------------------------
extern "C" void kernel_launch(void* const* d_in, const int* in_sizes, int n_in,
                              void* d_out, int out_size) {
    const float* x  = (const float*)d_in[0];   // (32, 1024, 256)
    const float* w1 = (const float*)d_in[1];   // (2048, 1024)
    const float* w2 = (const float*)d_in[2];   // (512, 2048)
    float* out = (float*)d_out;                // (32, 512, 256)

    float *w1t, *w2t, *a1, *a2;
    uint32_t *m1, *m2;
    uint8_t *l1, *l2;
    cudaGetSymbolAddress((void**)&w1t, g_w1t);
    cudaGetSymbolAddress((void**)&w2t, g_w2t);
    cudaGetSymbolAddress((void**)&a1, g_a1);
    cudaGetSymbolAddress((void**)&a2, g_a2);
    cudaGetSymbolAddress((void**)&m1, g_mask1);
    cudaGetSymbolAddress((void**)&m2, g_mask2);
    cudaGetSymbolAddress((void**)&l1, g_list1);
    cudaGetSymbolAddress((void**)&l2, g_list2);

    // smem: 1 weight buffer (129x64 f32) + 2 list buffers (64xLROW) = 51456 B
    const int SM = (CH + 1) * 64 * 4 + 2 * 64 * LROW;
    cudaFuncSetAttribute(sparse_add<NIN, NHID>,
                         cudaFuncAttributeMaxDynamicSharedMemorySize, SM);
    cudaFuncSetAttribute(sparse_add<NHID, NOUT>,
                         cudaFuncAttributeMaxDynamicSharedMemorySize, SM);

    init_tables<<<1, 64>>>();
    transpose_w<<<dim3(NIN / 32, NHID / 32), dim3(32, 8)>>>(w1, w1t, NHID, NIN);
    transpose_w<<<dim3(NHID / 32, NOUT / 32), dim3(32, 8)>>>(w2, w2t, NOUT, NHID);
    build_mask1<<<dim3(TT / 32, NIN / 32, B_), 256>>>(x, m1);
    list_build<NIN><<<B_ * TT / 256, 256>>>(m1, l1);

    // fc1: ordered sparse accumulation of w1t rows
    sparse_add<NIN, NHID>
        <<<dim3(NHID / 64, TT / 64, B_), 256, SM>>>(l1, w1t, a1);

    // psp1 + scan1 -> hidden spike masks -> lists
    psp_scan<true><<<dim3(NHID / 32, B_), 256>>>(a1, nullptr, m2, NHID);
    list_build<NHID><<<B_ * TT / 256, 256>>>(m2, l2);

    // fc2: ordered sparse accumulation of w2t rows
    sparse_add<NHID, NOUT>
        <<<dim3(NOUT / 64, TT / 64, B_), 256, SM>>>(l2, w2t, a2);

    // psp2 + scan2 -> d_out (b, o, t)
    psp_scan<false><<<dim3(NOUT / 32, B_), 256>>>(a2, out, nullptr, NOUT);
}

// round 16
// speedup vs baseline: 1.0779x; 1.0779x over previous
#include <cuda_runtime.h>
#include <math.h>
#include <stdint.h>

#define B_    32
#define NIN   1024
#define NHID  2048
#define NOUT  512
#define TT    256
#define KLEN  62          // truncated alpha kernel length (indices 0..61), tau=8
#define THETA 10.0f
#define PAD   64          // zero history rows in psp tile
#define CH    128         // k-chunk size for sparse GEMM
#define LROW  144         // list row bytes: u32 count @0, uint8 idx @4

// ---------------- scratch (alloc-free: __device__ globals) ----------------
__device__ float g_srm[64];
__device__ float g_ref[64];

__device__ float    g_w1t[(size_t)NIN * NHID];              // 8 MB  w1^T [i][h]
__device__ float    g_w2t[(size_t)NHID * NOUT];             // 4 MB  w2^T [h][o]
__device__ uint32_t g_mask1[(size_t)B_ * TT * (NIN / 32)];  // [b][t][kw]
__device__ uint32_t g_mask2[(size_t)B_ * TT * (NHID / 32)];
__device__ uint8_t  g_list1[(size_t)B_ * TT * (NIN / CH) * LROW];
__device__ uint8_t  g_list2[(size_t)B_ * TT * (NHID / CH) * LROW];
__device__ float    g_a1[(size_t)B_ * TT * NHID];           // 64 MB fc1 out
__device__ float    g_a2[(size_t)B_ * TT * NOUT];           // 16 MB fc2 out

// ---------------- helpers ---------------------------------------------------
__device__ __forceinline__ uint32_t smem_u32(const void* p) {
    uint32_t a;
    asm("{ .reg .u64 t; cvta.to.shared.u64 t, %1; cvt.u32.u64 %0, t; }"
        : "=r"(a) : "l"(p));
    return a;
}
__device__ __forceinline__ void cp16(uint32_t s, const void* g) {
    asm volatile("cp.async.cg.shared.global [%0], [%1], 16;" :: "r"(s), "l"(g));
}

// ---------------- kernel tables (match reference double-precision math) ----
__global__ void init_tables() {
    int k = threadIdx.x;
    if (k < 64) {
        double v = 0.0;
        if (k < KLEN) {
            double t = (double)k;
            v = (t / 8.0) * exp(1.0 - t / 8.0);
        }
        g_srm[k] = (float)v;
        g_ref[k] = (float)(-20.0 * v);
    }
}

// ---------------- weight transpose: out[c][r] = in[r][c] -------------------
__global__ __launch_bounds__(256) void transpose_w(const float* __restrict__ in,
                                                   float* __restrict__ out,
                                                   int R, int C) {
    __shared__ float tile[32][33];
    int c0 = blockIdx.x * 32;
    int r0 = blockIdx.y * 32;
    for (int r = threadIdx.y; r < 32; r += 8)
        tile[r][threadIdx.x] = in[(size_t)(r0 + r) * C + c0 + threadIdx.x];
    __syncthreads();
    for (int r = threadIdx.y; r < 32; r += 8)
        out[(size_t)(c0 + r) * R + r0 + threadIdx.x] = tile[threadIdx.x][r];
}

// ---------------- input spike masks: mask1[b][t][kw], bit l = x[b][kw*32+l][t]
__global__ __launch_bounds__(256) void build_mask1(const float* __restrict__ x,
                                                   uint32_t* __restrict__ mask) {
    __shared__ float tile[32][33];
    int b  = blockIdx.z;
    int i0 = blockIdx.y * 32;
    int t0 = blockIdx.x * 32;
    int tid = threadIdx.x;
    for (int idx = tid; idx < 1024; idx += 256) {
        int r = idx >> 5, c = idx & 31;
        tile[r][c] = x[((size_t)b * NIN + i0 + r) * TT + t0 + c];
    }
    __syncthreads();
    int w = tid >> 5, lane = tid & 31;
#pragma unroll
    for (int q = 0; q < 4; q++) {
        int t = w * 4 + q;
        uint32_t word = __ballot_sync(0xFFFFFFFFu, tile[lane][t] != 0.0f);
        if (lane == 0)
            mask[((size_t)b * TT + t0 + t) * (NIN / 32) + (i0 >> 5)] = word;
    }
}

// ---------------- masks -> chunk-local index lists -------------------------
// Per (b,t,kc): LROW-byte row, u32 padded count at +0, uint8 idx (0..CH-1)
// at +4, padded to a multiple of 4 with sentinel CH (zero weight row).
// Order: word-ascending + ffs-ascending = ascending k.  One thread per (b,t).
template <int K>
__global__ __launch_bounds__(256) void list_build(const uint32_t* __restrict__ mask,
                                                  uint8_t* __restrict__ list) {
    int bt = blockIdx.x * 256 + threadIdx.x;          // 0 .. B_*TT-1
    constexpr int NCH = K / CH;
    const uint32_t* mr = mask + (size_t)bt * (K / 32);
    uint8_t* lr = list + (size_t)bt * NCH * LROW;
    for (int kc = 0; kc < NCH; kc++) {
        uint8_t* row = lr + kc * LROW + 4;
        int n = 0;
#pragma unroll
        for (int w = 0; w < CH / 32; w++) {
            uint32_t m = mr[kc * (CH / 32) + w];
            while (m) {
                int j = __ffs(m) - 1;
                m &= m - 1;
                row[n++] = (uint8_t)(w * 32 + j);
            }
        }
        while (n & 3) row[n++] = CH;                  // sentinel -> zero row
        *(uint32_t*)(lr + kc * LROW) = (uint32_t)n;
    }
}

// ---------------- exact sparse spike GEMM (list-driven) --------------------
// C[b][t][h] = sum over active k (ascending) of Wt[k][h]; bitwise identical to
// dense fp32 ascending-k accumulation (skipped terms exact zeros; sentinel
// adds exact +0.0 from the zero row).
// Block 256 thr, tile 64 t x 64 h.  Warp owns 8 t; lane owns 2 h (LDS.64).
// Weights single-buffered (smem 51.5KB -> 4 blocks/SM); lists double-buffered
// and prefetched during compute.
template <int K, int N>
__global__ __launch_bounds__(256) void sparse_add(const uint8_t* __restrict__ list,
                                                  const float* __restrict__ Wt,
                                                  float* __restrict__ C) {
    constexpr int HT   = 64;
    constexpr int NCH  = K / CH;
    constexpr int WSZ  = (CH + 1) * HT;  // floats: CH rows + zero row
    constexpr int LSZ  = 64 * LROW;      // bytes per list buffer
    extern __shared__ char smraw[];
    float*   wbuf = (float*)smraw;                     // single weight buffer
    uint8_t* lbuf = (uint8_t*)(smraw + WSZ * 4);       // [2][64][LROW]
    uint32_t sb   = smem_u32(smraw);
    const uint32_t LOFF = WSZ * 4;

    int b  = blockIdx.z;
    int t0 = blockIdx.y * 64;
    int h0 = blockIdx.x * HT;
    int tid = threadIdx.x, warp = tid >> 5, lane = tid & 31;

    // zero row (row CH) — written once, never overwritten by loads
    for (int i = tid; i < HT; i += 256) wbuf[CH * HT + i] = 0.0f;

    auto load_w = [&](int kc) {
#pragma unroll
        for (int it = 0; it < CH * HT / 4 / 256; it++) {      // 8 cp16/thread
            int idx = tid + it * 256;
            int row = idx / (HT / 4), c4 = idx % (HT / 4);
            cp16(sb + (uint32_t)(row * HT + c4 * 4) * 4,
                 Wt + (size_t)(kc * CH + row) * N + h0 + c4 * 4);
        }
    };
    auto load_l = [&](int kc, int buf) {
#pragma unroll
        for (int it = 0; it < 3; it++) {                      // 576 cp16 total
            int idx = tid + it * 256;
            if (idx < 64 * LROW / 16) {
                int t = idx / (LROW / 16), seg = idx % (LROW / 16);
                cp16(sb + LOFF + buf * LSZ + t * LROW + seg * 16,
                     list + ((size_t)((b * TT + t0 + t) * NCH + kc)) * LROW + seg * 16);
            }
        }
    };

    // prologue: chunk 0 weights + lists
    load_l(0, 0);
    load_w(0);
    asm volatile("cp.async.commit_group;" ::: "memory");
    asm volatile("cp.async.wait_group 0;" ::: "memory");
    __syncthreads();

    float acc[8][2];
#pragma unroll
    for (int i = 0; i < 8; i++) { acc[i][0] = 0.0f; acc[i][1] = 0.0f; }

    for (int kc = 0; kc < NCH; kc++) {
        int buf = kc & 1;
        // prefetch next lists into the other buffer (no WAR with compute)
        if (kc + 1 < NCH) {
            load_l(kc + 1, buf ^ 1);
            asm volatile("cp.async.commit_group;" ::: "memory");
        }

        const float* wb = wbuf + lane * 2;
#pragma unroll
        for (int tt = 0; tt < 8; tt++) {
            const uint8_t* lp = lbuf + buf * LSZ + (warp * 8 + tt) * LROW;
            int n = *(const uint32_t*)lp;             // padded, multiple of 4
            const uint8_t* ip = lp + 4;
            float a0 = acc[tt][0], a1 = acc[tt][1];
#pragma unroll 2
            for (int i = 0; i < n; i += 4) {
                uint32_t pk = *(const uint32_t*)(ip + i);
#pragma unroll
                for (int q = 0; q < 4; q++) {
                    int c = (pk >> (8 * q)) & 0xFF;   // 0..CH
                    float2 wv = *(const float2*)(wb + c * HT);
                    a0 += wv.x; a1 += wv.y;
                }
            }
            acc[tt][0] = a0; acc[tt][1] = a1;
        }

        if (kc + 1 < NCH) {
            __syncthreads();                          // WAR: wbuf fully consumed
            load_w(kc + 1);
            asm volatile("cp.async.commit_group;" ::: "memory");
            asm volatile("cp.async.wait_group 0;" ::: "memory");
            __syncthreads();                          // RAW: wbuf + lists ready
        }
    }

    float* Cb = C + ((size_t)b * TT + t0 + warp * 8) * N + h0 + lane * 2;
#pragma unroll
    for (int tt = 0; tt < 8; tt++)
        *(float2*)(Cb + (size_t)tt * N) = make_float2(acc[tt][0], acc[tt][1]);
}

// ---------------- fused PSP conv + threshold/refractory scan ---------------
template <bool MASKOUT>
__global__ __launch_bounds__(256) void psp_scan(const float* __restrict__ in,
                                                float* __restrict__ fout,
                                                uint32_t* __restrict__ mout,
                                                int C) {
    __shared__ float tile[TT + PAD][33];
    __shared__ float srm[64];
    __shared__ float ref[64];

    int b  = blockIdx.y;
    int c0 = blockIdx.x * 32;
    int tid = threadIdx.x;

    if (tid < 64)       srm[tid] = g_srm[tid];
    else if (tid < 128) ref[tid - 64] = g_ref[tid - 64];

    for (int idx = tid; idx < PAD * 32; idx += 256)
        tile[idx >> 5][idx & 31] = 0.0f;

    const float* pin = in + (size_t)b * TT * C + c0;
    for (int idx = tid; idx < TT * 32; idx += 256) {
        int t = idx >> 5, c = idx & 31;
        tile[PAD + t][c] = pin[(size_t)t * C + c];
    }
    __syncthreads();

    float acc[2][16];
    int cc[2], tt0[2];
#pragma unroll
    for (int j = 0; j < 2; j++) {
        int item = tid + 256 * j;
        int c  = item & 31;
        int t0 = (item >> 5) * 16;
        cc[j] = c; tt0[j] = t0;
#pragma unroll
        for (int i = 0; i < 16; i++) acc[j][i] = 0.0f;

#pragma unroll
        for (int g = 0; g < 4; g++) {
            float v[31];
            int base = PAD + t0 - 16 * (g + 1);
#pragma unroll
            for (int q = 0; q < 31; q++) v[q] = tile[base + q][c];
            int kkmax = (g == 3) ? 13 : 16;
#pragma unroll
            for (int kk = 1; kk <= 16; kk++) {
                if (kk > kkmax) break;
                float s = srm[16 * g + kk];
#pragma unroll
                for (int i = 0; i < 16; i++)
                    acc[j][i] += s * v[16 + i - kk];
            }
        }
    }
    __syncthreads();

#pragma unroll
    for (int j = 0; j < 2; j++)
#pragma unroll
        for (int i = 0; i < 16; i++)
            tile[PAD + tt0[j] + i][cc[j]] = acc[j][i];
    __syncthreads();

    // scan: one thread per channel, 61-bit spike-history mask.
    // u prefetched 8 at a time (independent LDS) to amortize smem latency.
    if (tid < 32) {
        int c = tid;
        unsigned long long hist = 0ull;
        const unsigned long long M61 = (1ull << 61) - 1ull;
        for (int t8 = 0; t8 < TT; t8 += 8) {
            float u8[8];
#pragma unroll
            for (int q = 0; q < 8; q++) u8[q] = tile[PAD + t8 + q][c];
#pragma unroll
            for (int q = 0; q < 8; q++) {
                float u = u8[q];
                unsigned long long m = hist;
                while (m) {
                    int j = __ffsll((long long)m) - 1;   // age = j+1
                    u += ref[j + 1];
                    m &= m - 1;
                }
                unsigned long long s = (u >= THETA) ? 1ull : 0ull;
                hist = ((hist << 1) | s) & M61;
                tile[PAD + t8 + q][c] = (float)s;
            }
        }
    }
    __syncthreads();

    if (MASKOUT) {
        int w = tid >> 5, lane = tid & 31;
#pragma unroll
        for (int q = 0; q < 32; q++) {
            int t = w * 32 + q;
            uint32_t word = __ballot_sync(0xFFFFFFFFu, tile[PAD + t][lane] != 0.0f);
            if (lane == 0)
                mout[((size_t)b * TT + t) * (C / 32) + (c0 >> 5)] = word;
        }
    } else {
        for (int idx = tid; idx < TT * 32; idx += 256) {
            int t = idx & 255, c = idx >> 8;        // t-fast: coalesced STG
            fout[((size_t)b * C + c0 + c) * TT + t] = tile[PAD + t][c];
        }
    }
}

// ---------------- launch ----------------------------------------------------
extern "C" void kernel_launch(void* const* d_in, const int* in_sizes, int n_in,
                              void* d_out, int out_size) {
    const float* x  = (const float*)d_in[0];   // (32, 1024, 256)
    const float* w1 = (const float*)d_in[1];   // (2048, 1024)
    const float* w2 = (const float*)d_in[2];   // (512, 2048)
    float* out = (float*)d_out;                // (32, 512, 256)

    float *w1t, *w2t, *a1, *a2;
    uint32_t *m1, *m2;
    uint8_t *l1, *l2;
    cudaGetSymbolAddress((void**)&w1t, g_w1t);
    cudaGetSymbolAddress((void**)&w2t, g_w2t);
    cudaGetSymbolAddress((void**)&a1, g_a1);
    cudaGetSymbolAddress((void**)&a2, g_a2);
    cudaGetSymbolAddress((void**)&m1, g_mask1);
    cudaGetSymbolAddress((void**)&m2, g_mask2);
    cudaGetSymbolAddress((void**)&l1, g_list1);
    cudaGetSymbolAddress((void**)&l2, g_list2);

    // smem: 1 weight buffer (129x64 f32) + 2 list buffers (64xLROW) = 51456 B
    const int SM = (CH + 1) * 64 * 4 + 2 * 64 * LROW;
    cudaFuncSetAttribute(sparse_add<NIN, NHID>,
                         cudaFuncAttributeMaxDynamicSharedMemorySize, SM);
    cudaFuncSetAttribute(sparse_add<NHID, NOUT>,
                         cudaFuncAttributeMaxDynamicSharedMemorySize, SM);

    init_tables<<<1, 64>>>();
    transpose_w<<<dim3(NIN / 32, NHID / 32), dim3(32, 8)>>>(w1, w1t, NHID, NIN);
    transpose_w<<<dim3(NHID / 32, NOUT / 32), dim3(32, 8)>>>(w2, w2t, NOUT, NHID);
    build_mask1<<<dim3(TT / 32, NIN / 32, B_), 256>>>(x, m1);
    list_build<NIN><<<B_ * TT / 256, 256>>>(m1, l1);

    // fc1: ordered sparse accumulation of w1t rows
    sparse_add<NIN, NHID>
        <<<dim3(NHID / 64, TT / 64, B_), 256, SM>>>(l1, w1t, a1);

    // psp1 + scan1 -> hidden spike masks -> lists
    psp_scan<true><<<dim3(NHID / 32, B_), 256>>>(a1, nullptr, m2, NHID);
    list_build<NHID><<<B_ * TT / 256, 256>>>(m2, l2);

    // fc2: ordered sparse accumulation of w2t rows
    sparse_add<NHID, NOUT>
        <<<dim3(NOUT / 64, TT / 64, B_), 256, SM>>>(l2, w2t, a2);

    // psp2 + scan2 -> d_out (b, o, t)
    psp_scan<false><<<dim3(NOUT / 32, B_), 256>>>(a2, out, nullptr, NOUT);
}

// round 17
// speedup vs baseline: 1.1551x; 1.0717x over previous
#include <cuda_runtime.h>
#include <math.h>
#include <stdint.h>

#define B_    32
#define NIN   1024
#define NHID  2048
#define NOUT  512
#define TT    256
#define KLEN  62          // truncated alpha kernel length (indices 0..61), tau=8
#define THETA 10.0f
#define PAD   64          // zero history rows in psp tile
#define CH    128         // k-chunk size for sparse GEMM
#define LROW  144         // list row bytes: u32 count @0, uint8 idx @4

// ---------------- scratch (alloc-free: __device__ globals) ----------------
__device__ float g_srm[64];
__device__ float g_ref[64];

__device__ float    g_w1t[(size_t)NIN * NHID];              // 8 MB  w1^T [i][h]
__device__ float    g_w2t[(size_t)NHID * NOUT];             // 4 MB  w2^T [h][o]
__device__ uint32_t g_mask1[(size_t)B_ * TT * (NIN / 32)];  // [b][t][kw]
__device__ uint32_t g_mask2[(size_t)B_ * TT * (NHID / 32)];
__device__ uint8_t  g_list1[(size_t)B_ * TT * (NIN / CH) * LROW];
__device__ uint8_t  g_list2[(size_t)B_ * TT * (NHID / CH) * LROW];
__device__ float    g_a1[(size_t)B_ * TT * NHID];           // 64 MB fc1 out
__device__ float    g_a2[(size_t)B_ * TT * NOUT];           // 16 MB fc2 out

// ---------------- helpers ---------------------------------------------------
__device__ __forceinline__ uint32_t smem_u32(const void* p) {
    uint32_t a;
    asm("{ .reg .u64 t; cvta.to.shared.u64 t, %1; cvt.u32.u64 %0, t; }"
        : "=r"(a) : "l"(p));
    return a;
}
__device__ __forceinline__ void cp16(uint32_t s, const void* g) {
    asm volatile("cp.async.cg.shared.global [%0], [%1], 16;" :: "r"(s), "l"(g));
}

// ---------------- weight transpose: out[c][r] = in[r][c] -------------------
// Also writes the SRM/refractory tables (deterministic identical values from
// every block -> benign duplicate writes; consumed much later by psp_scan).
__global__ __launch_bounds__(256) void transpose_w(const float* __restrict__ in,
                                                   float* __restrict__ out,
                                                   int R, int C) {
    int tid = threadIdx.y * 32 + threadIdx.x;
    if (tid < 64) {
        double v = 0.0;
        if (tid < KLEN) {
            double t = (double)tid;
            v = (t / 8.0) * exp(1.0 - t / 8.0);   // alpha(t), peak 1 at t=tau
        }
        g_srm[tid] = (float)v;            // mult = 1
        g_ref[tid] = (float)(-20.0 * v);  // mult = -scaleRef*theta = -20
    }

    __shared__ float tile[32][33];
    int c0 = blockIdx.x * 32;
    int r0 = blockIdx.y * 32;
    for (int r = threadIdx.y; r < 32; r += 8)
        tile[r][threadIdx.x] = in[(size_t)(r0 + r) * C + c0 + threadIdx.x];
    __syncthreads();
    for (int r = threadIdx.y; r < 32; r += 8)
        out[(size_t)(c0 + r) * R + r0 + threadIdx.x] = tile[threadIdx.x][r];
}

// ---------------- input spike masks: mask1[b][t][kw], bit l = x[b][kw*32+l][t]
__global__ __launch_bounds__(256) void build_mask1(const float* __restrict__ x,
                                                   uint32_t* __restrict__ mask) {
    __shared__ float tile[32][33];
    int b  = blockIdx.z;
    int i0 = blockIdx.y * 32;
    int t0 = blockIdx.x * 32;
    int tid = threadIdx.x;
    for (int idx = tid; idx < 1024; idx += 256) {
        int r = idx >> 5, c = idx & 31;
        tile[r][c] = x[((size_t)b * NIN + i0 + r) * TT + t0 + c];
    }
    __syncthreads();
    int w = tid >> 5, lane = tid & 31;
#pragma unroll
    for (int q = 0; q < 4; q++) {
        int t = w * 4 + q;
        uint32_t word = __ballot_sync(0xFFFFFFFFu, tile[lane][t] != 0.0f);
        if (lane == 0)
            mask[((size_t)b * TT + t0 + t) * (NIN / 32) + (i0 >> 5)] = word;
    }
}

// ---------------- masks -> chunk-local index lists (warp-parallel) ---------
// Warp per (b,t); lane per (chunk, word-in-chunk).  popcount + 4-lane shuffle
// prefix gives each word its write offset -> list bytes are bit-identical to
// the serial builder (word-ascending + ffs-ascending = ascending k; padded to
// a multiple of 4 with sentinel CH -> zero weight row).
template <int K>
__global__ __launch_bounds__(256) void list_build(const uint32_t* __restrict__ mask,
                                                  uint8_t* __restrict__ list) {
    constexpr int NCH = K / CH;
    constexpr int SLOTS = NCH * 4;                    // words total (32 or 64)
    int wid  = blockIdx.x * 8 + (threadIdx.x >> 5);   // warp = (b,t) index
    int lane = threadIdx.x & 31;
    const uint32_t* mr = mask + (size_t)wid * (K / 32);
    uint8_t* lr = list + (size_t)wid * NCH * LROW;

#pragma unroll
    for (int it = 0; it < SLOTS / 32; it++) {
        int slot = lane + 32 * it;
        int c = slot >> 2, w = slot & 3;
        uint32_t m = mr[c * 4 + w];
        int pc = __popc(m);
        // inclusive scan over the 4 lanes of this chunk group
        int s = pc;
        int t1 = __shfl_up_sync(0xFFFFFFFFu, s, 1);
        if ((lane & 3) >= 1) s += t1;
        int t2 = __shfl_up_sync(0xFFFFFFFFu, s, 2);
        if ((lane & 3) >= 2) s += t2;
        int excl  = s - pc;                           // offset for this word
        int total = __shfl_sync(0xFFFFFFFFu, s, lane | 3);  // chunk total
        uint8_t* row = lr + c * LROW;
        int o = 4 + excl;
        while (m) {
            int j = __ffs(m) - 1;
            m &= m - 1;
            row[o++] = (uint8_t)(w * 32 + j);
        }
        if ((lane & 3) == 3) {                        // last word pads + count
            int npad = (total + 3) & ~3;
            for (int q = total; q < npad; q++) row[4 + q] = CH;  // sentinel
            *(uint32_t*)row = (uint32_t)npad;
        }
    }
}

// ---------------- exact sparse spike GEMM (list-driven) --------------------
// C[b][t][h] = sum over active k (ascending) of Wt[k][h]; bitwise identical to
// dense fp32 ascending-k accumulation (skipped terms exact zeros; sentinel
// adds exact +0.0 from the zero row).
// Block 256 thr, tile 64 t x 64 h.  Warp owns 8 t; lane owns 2 h (LDS.64).
// Weights single-buffered (smem 51.5KB -> 4 blocks/SM); lists double-buffered
// and prefetched during compute.
template <int K, int N>
__global__ __launch_bounds__(256) void sparse_add(const uint8_t* __restrict__ list,
                                                  const float* __restrict__ Wt,
                                                  float* __restrict__ C) {
    constexpr int HT   = 64;
    constexpr int NCH  = K / CH;
    constexpr int WSZ  = (CH + 1) * HT;  // floats: CH rows + zero row
    constexpr int LSZ  = 64 * LROW;      // bytes per list buffer
    extern __shared__ char smraw[];
    float*   wbuf = (float*)smraw;                     // single weight buffer
    uint8_t* lbuf = (uint8_t*)(smraw + WSZ * 4);       // [2][64][LROW]
    uint32_t sb   = smem_u32(smraw);
    const uint32_t LOFF = WSZ * 4;

    int b  = blockIdx.z;
    int t0 = blockIdx.y * 64;
    int h0 = blockIdx.x * HT;
    int tid = threadIdx.x, warp = tid >> 5, lane = tid & 31;

    // zero row (row CH) — written once, never overwritten by loads
    for (int i = tid; i < HT; i += 256) wbuf[CH * HT + i] = 0.0f;

    auto load_w = [&](int kc) {
#pragma unroll
        for (int it = 0; it < CH * HT / 4 / 256; it++) {      // 8 cp16/thread
            int idx = tid + it * 256;
            int row = idx / (HT / 4), c4 = idx % (HT / 4);
            cp16(sb + (uint32_t)(row * HT + c4 * 4) * 4,
                 Wt + (size_t)(kc * CH + row) * N + h0 + c4 * 4);
        }
    };
    auto load_l = [&](int kc, int buf) {
#pragma unroll
        for (int it = 0; it < 3; it++) {                      // 576 cp16 total
            int idx = tid + it * 256;
            if (idx < 64 * LROW / 16) {
                int t = idx / (LROW / 16), seg = idx % (LROW / 16);
                cp16(sb + LOFF + buf * LSZ + t * LROW + seg * 16,
                     list + ((size_t)((b * TT + t0 + t) * NCH + kc)) * LROW + seg * 16);
            }
        }
    };

    // prologue: chunk 0 weights + lists
    load_l(0, 0);
    load_w(0);
    asm volatile("cp.async.commit_group;" ::: "memory");
    asm volatile("cp.async.wait_group 0;" ::: "memory");
    __syncthreads();

    float acc[8][2];
#pragma unroll
    for (int i = 0; i < 8; i++) { acc[i][0] = 0.0f; acc[i][1] = 0.0f; }

    for (int kc = 0; kc < NCH; kc++) {
        int buf = kc & 1;
        // prefetch next lists into the other buffer (no WAR with compute)
        if (kc + 1 < NCH) {
            load_l(kc + 1, buf ^ 1);
            asm volatile("cp.async.commit_group;" ::: "memory");
        }

        const float* wb = wbuf + lane * 2;
#pragma unroll
        for (int tt = 0; tt < 8; tt++) {
            const uint8_t* lp = lbuf + buf * LSZ + (warp * 8 + tt) * LROW;
            int n = *(const uint32_t*)lp;             // padded, multiple of 4
            const uint8_t* ip = lp + 4;
            float a0 = acc[tt][0], a1 = acc[tt][1];
#pragma unroll 2
            for (int i = 0; i < n; i += 4) {
                uint32_t pk = *(const uint32_t*)(ip + i);
#pragma unroll
                for (int q = 0; q < 4; q++) {
                    int c = (pk >> (8 * q)) & 0xFF;   // 0..CH
                    float2 wv = *(const float2*)(wb + c * HT);
                    a0 += wv.x; a1 += wv.y;
                }
            }
            acc[tt][0] = a0; acc[tt][1] = a1;
        }

        if (kc + 1 < NCH) {
            __syncthreads();                          // WAR: wbuf fully consumed
            load_w(kc + 1);
            asm volatile("cp.async.commit_group;" ::: "memory");
            asm volatile("cp.async.wait_group 0;" ::: "memory");
            __syncthreads();                          // RAW: wbuf + lists ready
        }
    }

    float* Cb = C + ((size_t)b * TT + t0 + warp * 8) * N + h0 + lane * 2;
#pragma unroll
    for (int tt = 0; tt < 8; tt++)
        *(float2*)(Cb + (size_t)tt * N) = make_float2(acc[tt][0], acc[tt][1]);
}

// ---------------- fused PSP conv + threshold/refractory scan ---------------
template <bool MASKOUT>
__global__ __launch_bounds__(256) void psp_scan(const float* __restrict__ in,
                                                float* __restrict__ fout,
                                                uint32_t* __restrict__ mout,
                                                int C) {
    __shared__ float tile[TT + PAD][33];
    __shared__ float srm[64];
    __shared__ float ref[64];

    int b  = blockIdx.y;
    int c0 = blockIdx.x * 32;
    int tid = threadIdx.x;

    if (tid < 64)       srm[tid] = g_srm[tid];
    else if (tid < 128) ref[tid - 64] = g_ref[tid - 64];

    for (int idx = tid; idx < PAD * 32; idx += 256)
        tile[idx >> 5][idx & 31] = 0.0f;

    const float* pin = in + (size_t)b * TT * C + c0;
    for (int idx = tid; idx < TT * 32; idx += 256) {
        int t = idx >> 5, c = idx & 31;
        tile[PAD + t][c] = pin[(size_t)t * C + c];
    }
    __syncthreads();

    float acc[2][16];
    int cc[2], tt0[2];
#pragma unroll
    for (int j = 0; j < 2; j++) {
        int item = tid + 256 * j;
        int c  = item & 31;
        int t0 = (item >> 5) * 16;
        cc[j] = c; tt0[j] = t0;
#pragma unroll
        for (int i = 0; i < 16; i++) acc[j][i] = 0.0f;

#pragma unroll
        for (int g = 0; g < 4; g++) {
            float v[31];
            int base = PAD + t0 - 16 * (g + 1);
#pragma unroll
            for (int q = 0; q < 31; q++) v[q] = tile[base + q][c];
            int kkmax = (g == 3) ? 13 : 16;
#pragma unroll
            for (int kk = 1; kk <= 16; kk++) {
                if (kk > kkmax) break;
                float s = srm[16 * g + kk];
#pragma unroll
                for (int i = 0; i < 16; i++)
                    acc[j][i] += s * v[16 + i - kk];
            }
        }
    }
    __syncthreads();

#pragma unroll
    for (int j = 0; j < 2; j++)
#pragma unroll
        for (int i = 0; i < 16; i++)
            tile[PAD + tt0[j] + i][cc[j]] = acc[j][i];
    __syncthreads();

    // scan: one thread per channel, 61-bit spike-history mask.
    // u prefetched 8 at a time (independent LDS) to amortize smem latency.
    if (tid < 32) {
        int c = tid;
        unsigned long long hist = 0ull;
        const unsigned long long M61 = (1ull << 61) - 1ull;
        for (int t8 = 0; t8 < TT; t8 += 8) {
            float u8[8];
#pragma unroll
            for (int q = 0; q < 8; q++) u8[q] = tile[PAD + t8 + q][c];
#pragma unroll
            for (int q = 0; q < 8; q++) {
                float u = u8[q];
                unsigned long long m = hist;
                while (m) {
                    int j = __ffsll((long long)m) - 1;   // age = j+1
                    u += ref[j + 1];
                    m &= m - 1;
                }
                unsigned long long s = (u >= THETA) ? 1ull : 0ull;
                hist = ((hist << 1) | s) & M61;
                tile[PAD + t8 + q][c] = (float)s;
            }
        }
    }
    __syncthreads();

    if (MASKOUT) {
        int w = tid >> 5, lane = tid & 31;
#pragma unroll
        for (int q = 0; q < 32; q++) {
            int t = w * 32 + q;
            uint32_t word = __ballot_sync(0xFFFFFFFFu, tile[PAD + t][lane] != 0.0f);
            if (lane == 0)
                mout[((size_t)b * TT + t) * (C / 32) + (c0 >> 5)] = word;
        }
    } else {
        for (int idx = tid; idx < TT * 32; idx += 256) {
            int t = idx & 255, c = idx >> 8;        // t-fast: coalesced STG
            fout[((size_t)b * C + c0 + c) * TT + t] = tile[PAD + t][c];
        }
    }
}

// ---------------- launch ----------------------------------------------------
extern "C" void kernel_launch(void* const* d_in, const int* in_sizes, int n_in,
                              void* d_out, int out_size) {
    const float* x  = (const float*)d_in[0];   // (32, 1024, 256)
    const float* w1 = (const float*)d_in[1];   // (2048, 1024)
    const float* w2 = (const float*)d_in[2];   // (512, 2048)
    float* out = (float*)d_out;                // (32, 512, 256)

    float *w1t, *w2t, *a1, *a2;
    uint32_t *m1, *m2;
    uint8_t *l1, *l2;
    cudaGetSymbolAddress((void**)&w1t, g_w1t);
    cudaGetSymbolAddress((void**)&w2t, g_w2t);
    cudaGetSymbolAddress((void**)&a1, g_a1);
    cudaGetSymbolAddress((void**)&a2, g_a2);
    cudaGetSymbolAddress((void**)&m1, g_mask1);
    cudaGetSymbolAddress((void**)&m2, g_mask2);
    cudaGetSymbolAddress((void**)&l1, g_list1);
    cudaGetSymbolAddress((void**)&l2, g_list2);

    // smem: 1 weight buffer (129x64 f32) + 2 list buffers (64xLROW) = 51456 B
    const int SM = (CH + 1) * 64 * 4 + 2 * 64 * LROW;
    cudaFuncSetAttribute(sparse_add<NIN, NHID>,
                         cudaFuncAttributeMaxDynamicSharedMemorySize, SM);
    cudaFuncSetAttribute(sparse_add<NHID, NOUT>,
                         cudaFuncAttributeMaxDynamicSharedMemorySize, SM);

    // transposes also write the SRM/ref tables (consumed later by psp_scan)
    transpose_w<<<dim3(NIN / 32, NHID / 32), dim3(32, 8)>>>(w1, w1t, NHID, NIN);
    transpose_w<<<dim3(NHID / 32, NOUT / 32), dim3(32, 8)>>>(w2, w2t, NOUT, NHID);
    build_mask1<<<dim3(TT / 32, NIN / 32, B_), 256>>>(x, m1);
    list_build<NIN><<<B_ * TT / 8, 256>>>(m1, l1);

    // fc1: ordered sparse accumulation of w1t rows
    sparse_add<NIN, NHID>
        <<<dim3(NHID / 64, TT / 64, B_), 256, SM>>>(l1, w1t, a1);

    // psp1 + scan1 -> hidden spike masks -> lists
    psp_scan<true><<<dim3(NHID / 32, B_), 256>>>(a1, nullptr, m2, NHID);
    list_build<NHID><<<B_ * TT / 8, 256>>>(m2, l2);

    // fc2: ordered sparse accumulation of w2t rows
    sparse_add<NHID, NOUT>
        <<<dim3(NOUT / 64, TT / 64, B_), 256, SM>>>(l2, w2t, a2);

    // psp2 + scan2 -> d_out (b, o, t)
    psp_scan<false><<<dim3(NOUT / 32, B_), 256>>>(a2, out, nullptr, NOUT);
}